// round 11
// baseline (speedup 1.0000x reference)
#include <cuda_runtime.h>
#include <cuda_fp16.h>

#define NN 50000
#define EE 800000
#define SC 5
#define NBC 8
#define HC 64
#define NWC 128
#define TBINS 1024
#define RMAXF 5.0f

#define NODE_BLOCKS 196         // 196*256 >= NN

// ---------------- device scratch ----------------
// g_zb layout: [0,NN) degree->cursor; [NN,NN+5) species counts; [NN+16, NN+16+NODE_BLOCKS) lookback states
__device__ int g_zb[NN + 16 + NODE_BLOCKS];
__device__ int g_off[NN + 1];
__device__ int g_scur[SC];
__device__ int g_nsort[NN];
__device__ uint4 g_erec[EE];             // packed CSR edge record: p | sh01 | (spec<<16|sh2) | sender
__device__ float g_hs[NN * 32];
__device__ float g_hv[NN * 96];
__device__ __half2 g_feath[NN * 64];     // layer1 feats: (es,ev0),(ev1,ev2)
__device__ float g_res1s[NN * 32];
__device__ __half2 g_tab0h[TBINS * 32];  // layer0 LUT (w1, w3)  — 128 KB, L1-resident
__device__ __half2 g_tab1h[TBINS * 32];  // layer1 LUT (w1, w2)
__device__ float g_s0hsl[SC * 32];
__device__ float g_s0res[SC * 64];
__device__ float g_wcomb[32];            // readout combined weights

__device__ __forceinline__ float silu(float x) { return x / (1.0f + __expf(-x)); }

// ---------------- hist: degree + species counts ----------------
__global__ void k_hist(const float* __restrict__ evec, const int* __restrict__ recv,
                       const int* __restrict__ species) {
    int e = blockIdx.x * blockDim.x + threadIdx.x;
    if (e < NN) atomicAdd(&g_zb[NN + species[e]], 1);
    if (e >= EE) return;
    float x = evec[e * 3], y = evec[e * 3 + 1], z = evec[e * 3 + 2];
    if (x * x + y * y + z * z < RMAXF * RMAXF) atomicAdd(&g_zb[recv[e]], 1);
}

// ---------------- single-pass scan, warp-parallel decoupled lookback ----------------
#define FLAGP 0x40000000u
#define FLAGX 0x80000000u
#define VALM  0x3FFFFFFFu

__global__ void __launch_bounds__(256) k_scan() {
    __shared__ int ws[8];
    __shared__ int s_tot, s_off;
    int b = blockIdx.x, t = threadIdx.x;
    int lane = t & 31, wid = t >> 5;
    int idx = b * 256 + t;
    int v = (idx < NN) ? g_zb[idx] : 0;
    int x = v;
#pragma unroll
    for (int d = 1; d < 32; d <<= 1) {
        int y = __shfl_up_sync(0xffffffffu, x, d);
        if (lane >= d) x += y;
    }
    if (lane == 31) ws[wid] = x;
    __syncthreads();
    if (wid == 0 && lane < 8) {
        int s = ws[lane];
#pragma unroll
        for (int d = 1; d < 8; d <<= 1) {
            int y = __shfl_up_sync(0xffu, s, d);
            if (lane >= d) s += y;
        }
        ws[lane] = s;
    }
    __syncthreads();
    int incl = x + (wid > 0 ? ws[wid - 1] : 0);
    if (t == 255) s_tot = incl;
    __syncthreads();
    unsigned int* look = reinterpret_cast<unsigned int*>(&g_zb[NN + 16]);
    if (wid == 0) {
        if (b == 0) {
            if (lane == 0) {
                int a2 = 0;   // species prefix (hist done)
                for (int s = 0; s < SC; s++) { g_scur[s] = a2; a2 += g_zb[NN + s]; }
                s_off = 0;
                atomicExch(&look[0], (unsigned)s_tot | FLAGX);
            }
        } else {
            if (lane == 0) atomicExch(&look[b], (unsigned)s_tot | FLAGP);
            int run = 0, j = b;
            while (true) {
                int pidx = j - 1 - lane;
                unsigned st = FLAGX;   // OOB lanes contribute value 0 with X-flag
                if (pidx >= 0) {
                    while ((((st = atomicAdd(&look[pidx], 0u))) & (FLAGP | FLAGX)) == 0u)
                        __nanosleep(32);
                }
                unsigned xmask = __ballot_sync(0xffffffffu, (st & FLAGX) != 0u);
                int val = (int)(st & VALM);
                if (xmask) {
                    int firstx = __ffs(xmask) - 1;   // nearest predecessor with inclusive sum
                    int contrib = (lane <= firstx) ? val : 0;
#pragma unroll
                    for (int d = 16; d > 0; d >>= 1)
                        contrib += __shfl_xor_sync(0xffffffffu, contrib, d);
                    run += contrib;
                    break;
                } else {
                    int contrib = val;
#pragma unroll
                    for (int d = 16; d > 0; d >>= 1)
                        contrib += __shfl_xor_sync(0xffffffffu, contrib, d);
                    run += contrib;
                    j -= 32;
                }
            }
            if (lane == 0) {
                s_off = run;
                atomicExch(&look[b], (unsigned)(run + s_tot) | FLAGX);
            }
        }
        if (b == NODE_BLOCKS - 1 && lane == 0) g_off[NN] = s_off + s_tot;
    }
    __syncthreads();
    if (idx < NN) {
        int o = incl - v + s_off;
        g_off[idx] = o;
        g_zb[idx] = o;   // cursor for scatter
    }
}

// ---------------- scatter: packed 16B record + species-sorted node list ----------------
__global__ void k_scatter(const float* __restrict__ evec, const int* __restrict__ senders,
                          const int* __restrict__ recv, const int* __restrict__ species) {
    int e = blockIdx.x * blockDim.x + threadIdx.x;
    if (e < NN) {
        int pos = atomicAdd(&g_scur[species[e]], 1);
        g_nsort[pos] = e;
    }
    if (e >= EE) return;
    float x = evec[e * 3], y = evec[e * 3 + 1], z = evec[e * 3 + 2];
    float r2 = x * x + y * y + z * z;
    if (r2 >= RMAXF * RMAXF) return;
    float r = sqrtf(r2 + 1e-12f);
    float ir = 1.0f / r;
    const float SQ3 = 1.7320508075688772f;
    int s = senders[e];
    int pos = atomicAdd(&g_zb[recv[e]], 1);
    uint4 rec;
    rec.x = __float_as_uint(r * ((float)(TBINS - 1) / RMAXF));
    __half2 h01 = __floats2half2_rn(SQ3 * x * ir, SQ3 * y * ir);
    rec.y = *reinterpret_cast<unsigned int*>(&h01);
    __half h2 = __float2half_rn(SQ3 * z * ir);
    rec.z = ((unsigned int)species[s] << 16) | (unsigned int)__half_as_ushort(h2);
    rec.w = (unsigned int)s;
    g_erec[pos] = rec;
}

// ---------------- radial-MLP LUT (fp16 rows, both layers) ----------------
__global__ void k_build_table(const float* __restrict__ mlp_w0,
                              const float* __restrict__ mlp_w1,
                              const float* __restrict__ mlp_w2) {
    __shared__ float a1[HC];
    __shared__ float a2[HC];
    __shared__ float eemb[NBC];
    __shared__ float sacc[128];
    int bin = blockIdx.x;
    int l = blockIdx.y;
    int tid = threadIdx.x;
    const float* w0 = mlp_w0 + l * NBC * HC;
    const float* w1 = mlp_w1 + l * HC * HC;
    const float* w2 = mlp_w2 + l * HC * NWC;
    if (tid < NBC) {
        float r = (float)bin * (RMAXF / (float)(TBINS - 1));
        float rs = fmaxf(r, 1e-6f);
        float ir = 1.0f / rs;
        float xr = rs * (1.0f / RMAXF);
        float x3 = xr * xr * xr, x6 = x3 * x3, x7 = x6 * xr, x8 = x7 * xr;
        float env = 1.0f - 28.0f * x6 + 48.0f * x7 - 21.0f * x8;
        const float PI_ = 3.14159265358979323846f;
        eemb[tid] = 0.6324555320336759f * ir * env * sinf(PI_ * xr * (float)(tid + 1));
    }
    __syncthreads();
    if (tid < HC) {
        float acc = 0.f;
#pragma unroll
        for (int k = 0; k < NBC; k++) acc += eemb[k] * w0[k * HC + tid];
        a1[tid] = silu(acc * 0.35355339059327373f);
    }
    __syncthreads();
    if (tid < HC) {
        float acc = 0.f;
#pragma unroll 8
        for (int k = 0; k < HC; k++) acc += a1[k] * w1[k * HC + tid];
        a2[tid] = silu(acc * 0.125f);
    }
    __syncthreads();
    {
        float acc = 0.f;
#pragma unroll 8
        for (int k = 0; k < HC; k++) acc += a2[k] * w2[k * NWC + tid];
        sacc[tid] = acc;
    }
    __syncthreads();
    if (tid < 32) {
        if (l == 0)
            g_tab0h[bin * 32 + tid] = __floats2half2_rn(sacc[tid], sacc[64 + tid]);
        else
            g_tab1h[bin * 32 + tid] = __floats2half2_rn(sacc[tid], sacc[32 + tid]);
    }
}

// ---------------- layer0 species-pure node prep + readout wcomb ----------------
__global__ void k_spec0(const float* __restrict__ embed_w,
                        const float* __restrict__ w_lin1_s,
                        const float* __restrict__ w_res_s,
                        const float* __restrict__ w_out1,
                        const float* __restrict__ w_out2) {
    int w = threadIdx.x >> 5, lane = threadIdx.x & 31;
    if (w < SC) {
        float a_hs = 0.f, a_rs0 = 0.f, a_rs1 = 0.f;
#pragma unroll 4
        for (int u = 0; u < 32; u++) {
            float x = embed_w[w * 32 + u] * 0.4472135954999579f;
            a_hs += x * w_lin1_s[u * 32 + lane];
            const float* rs = w_res_s + (size_t)(u * SC + w) * 64;
            a_rs0 += x * rs[lane];
            a_rs1 += x * rs[32 + lane];
        }
        g_s0hsl[w * 32 + lane] = a_hs * 0.17677669529663687f;
        g_s0res[w * 64 + lane] = a_rs0 * 0.07905694150420949f;
        g_s0res[w * 64 + 32 + lane] = a_rs1 * 0.07905694150420949f;
    } else if (w == SC) {
        float acc = 0.f;
#pragma unroll
        for (int k = 0; k < 16; k++) acc += w_out1[lane * 16 + k] * w_out2[k];
        g_wcomb[lane] = acc;
    }
}

// ---------------- fused layer0: pipelined gather + lin2 + residual + gate ----------------
__global__ void __launch_bounds__(128, 8) k_gfused0(const int* __restrict__ species,
                                                    const float* __restrict__ w_lin2_s,
                                                    const float* __restrict__ w_lin2_v) {
    int n = (blockIdx.x * blockDim.x + threadIdx.x) >> 5;
    int lane = threadIdx.x & 31;
    if (n >= NN) return;
    float sr[SC];
#pragma unroll
    for (int s = 0; s < SC; s++) sr[s] = g_s0hsl[s * 32 + lane];
    int e = g_off[n], end = g_off[n + 1];
    float a0 = 0.f, c3x = 0.f, c3y = 0.f, c3z = 0.f;
    uint4 cur[4];
    if (e + 3 < end) {
#pragma unroll
        for (int k = 0; k < 4; k++) cur[k] = __ldcs(&g_erec[e + k]);
    }
    while (e + 3 < end) {
        int en = e + 4;
        uint4 nxt[4];
        bool hn = (en + 3 < end);
        if (hn) {
#pragma unroll
            for (int k = 0; k < 4; k++) nxt[k] = __ldcs(&g_erec[en + k]);
        }
#pragma unroll
        for (int k = 0; k < 4; k++) {
            float p = __uint_as_float(cur[k].x);
            int i = (int)p;
            float f = p - (float)i;
            float2 t0 = __half22float2(g_tab0h[i * 32 + lane]);
            float2 t1 = __half22float2(g_tab0h[(i + 1) * 32 + lane]);
            float2 sh = __half22float2(*reinterpret_cast<const __half2*>(&cur[k].y));
            float sh2 = __half2float(__ushort_as_half((unsigned short)(cur[k].z & 0xffffu)));
            int sp = cur[k].z >> 16;
            float es = sr[0];
            es = (sp == 1) ? sr[1] : es;
            es = (sp == 2) ? sr[2] : es;
            es = (sp == 3) ? sr[3] : es;
            es = (sp == 4) ? sr[4] : es;
            float w1 = fmaf(f, t1.x - t0.x, t0.x);
            float w3 = fmaf(f, t1.y - t0.y, t0.y);
            a0 += w1 * es;
            float wv = w3 * es;
            c3x += wv * sh.x; c3y += wv * sh.y; c3z += wv * sh2;
        }
        if (hn) {
#pragma unroll
            for (int k = 0; k < 4; k++) cur[k] = nxt[k];
        }
        e = en;
    }
    for (; e < end; e++) {
        uint4 rA = __ldcs(&g_erec[e]);
        float p = __uint_as_float(rA.x);
        int i = (int)p;
        float f = p - (float)i;
        float2 t0 = __half22float2(g_tab0h[i * 32 + lane]);
        float2 t1 = __half22float2(g_tab0h[(i + 1) * 32 + lane]);
        float2 sh = __half22float2(*reinterpret_cast<const __half2*>(&rA.y));
        float sh2 = __half2float(__ushort_as_half((unsigned short)(rA.z & 0xffffu)));
        int sp = rA.z >> 16;
        float es = sr[0];
        es = (sp == 1) ? sr[1] : es;
        es = (sp == 2) ? sr[2] : es;
        es = (sp == 3) ? sr[3] : es;
        es = (sp == 4) ? sr[4] : es;
        float w1 = fmaf(f, t1.x - t0.x, t0.x);
        float w3 = fmaf(f, t1.y - t0.y, t0.y);
        a0 += w1 * es;
        float wv = w3 * es;
        c3x += wv * sh.x; c3y += wv * sh.y; c3z += wv * sh2;
    }
    // ---- fused lin2 + residual + gate via shuffle contraction ----
    float s0 = 0.f, s1 = 0.f, v0 = 0.f, v1 = 0.f, v2 = 0.f;
#pragma unroll 4
    for (int j = 0; j < 32; j++) {
        float xj = __shfl_sync(0xffffffffu, a0, j);
        float c0 = __shfl_sync(0xffffffffu, c3x, j);
        float c1 = __shfl_sync(0xffffffffu, c3y, j);
        float c2 = __shfl_sync(0xffffffffu, c3z, j);
        float wa = w_lin2_s[j * 64 + lane];
        float wb = w_lin2_s[j * 64 + 32 + lane];
        float wc = w_lin2_v[j * 32 + lane];
        s0 += xj * wa;
        s1 += xj * wb;
        v0 += c0 * wc; v1 += c1 * wc; v2 += c2 * wc;
    }
    const float SC_ = 0.0078125f;
    int sp = species[n];
    float hs = silu(s0 * SC_ + g_s0res[sp * 64 + lane]);
    float gate = silu(s1 * SC_ + g_s0res[sp * 64 + 32 + lane]);
    g_hs[n * 32 + lane] = hs;
    g_hv[(n * 3 + 0) * 32 + lane] = v0 * SC_ * gate;
    g_hv[(n * 3 + 1) * 32 + lane] = v1 * SC_ * gate;
    g_hv[(n * 3 + 2) * 32 + lane] = v2 * SC_ * gate;
}

// ---------------- layer1 prep ----------------
__global__ void __launch_bounds__(256) k_prep1(const int* __restrict__ species,
                                               const float* __restrict__ w_res_s,
                                               const float* __restrict__ w_lin1_s,
                                               const float* __restrict__ w_lin1_v) {
    int w = (blockIdx.x * blockDim.x + threadIdx.x) >> 5;
    int lane = threadIdx.x & 31;
    int base = w * 8;
    if (base >= NN) return;
    int nid[8], sp[8];
#pragma unroll
    for (int g = 0; g < 8; g++) { nid[g] = g_nsort[base + g]; sp[g] = species[nid[g]]; }
    bool uni = true;
#pragma unroll
    for (int g = 1; g < 8; g++) uni = uni && (sp[g] == sp[0]);
    const float* Wl1s = w_lin1_s + 1024;
    const float* Wl1v = w_lin1_v + 1024;
    float a_hs[8] = {0}, a_rs0[8] = {0}, a_hv[8][3] = {{0}};
#pragma unroll 2
    for (int uc = 0; uc < 8; uc++) {
        int u0 = uc * 4;
        float ws[4], wv[4], wr0[4];
#pragma unroll
        for (int d = 0; d < 4; d++) {
            ws[d] = Wl1s[(u0 + d) * 32 + lane];
            wv[d] = Wl1v[(u0 + d) * 32 + lane];
        }
        if (uni) {
#pragma unroll
            for (int d = 0; d < 4; d++)
                wr0[d] = w_res_s[(size_t)(((32 + u0 + d) * SC) + sp[0]) * 64 + lane];
        }
#pragma unroll
        for (int g = 0; g < 8; g++) {
            float r0[4];
            if (uni) {
#pragma unroll
                for (int d = 0; d < 4; d++) r0[d] = wr0[d];
            } else {
#pragma unroll
                for (int d = 0; d < 4; d++)
                    r0[d] = w_res_s[(size_t)(((32 + u0 + d) * SC) + sp[g]) * 64 + lane];
            }
            float4 xs = *reinterpret_cast<const float4*>(&g_hs[nid[g] * 32 + u0]);
            float xa[4] = {xs.x, xs.y, xs.z, xs.w};
#pragma unroll
            for (int d = 0; d < 4; d++) {
                a_hs[g] += xa[d] * ws[d];
                a_rs0[g] += xa[d] * r0[d];
            }
#pragma unroll
            for (int i = 0; i < 3; i++) {
                float4 xv = *reinterpret_cast<const float4*>(&g_hv[(nid[g] * 3 + i) * 32 + u0]);
                a_hv[g][i] += xv.x * wv[0] + xv.y * wv[1] + xv.z * wv[2] + xv.w * wv[3];
            }
        }
    }
    const float IS32 = 0.17677669529663687f;
    const float IS160 = 0.07905694150420949f;
#pragma unroll
    for (int g = 0; g < 8; g++) {
        int n = nid[g];
        g_feath[n * 64 + lane * 2] = __floats2half2_rn(a_hs[g] * IS32, a_hv[g][0] * IS32);
        g_feath[n * 64 + lane * 2 + 1] = __floats2half2_rn(a_hv[g][1] * IS32, a_hv[g][2] * IS32);
        g_res1s[n * 32 + lane] = a_rs0[g] * IS160;
    }
}

// ---------------- fused layer1: pipelined gather + lin2 + residual + readout ----------------
__global__ void __launch_bounds__(128, 8) k_gfused1(const float* __restrict__ w_lin2_s,
                                                    float* __restrict__ out) {
    int n = (blockIdx.x * blockDim.x + threadIdx.x) >> 5;
    int lane = threadIdx.x & 31;
    if (n >= NN) return;
    int e = g_off[n], end = g_off[n + 1];
    float a0 = 0.f, a1 = 0.f;
    uint4 cur[4];
    if (e + 3 < end) {
#pragma unroll
        for (int k = 0; k < 4; k++) cur[k] = __ldcs(&g_erec[e + k]);
    }
    while (e + 3 < end) {
        int en = e + 4;
        uint4 nxt[4];
        bool hn = (en + 3 < end);
        if (hn) {
#pragma unroll
            for (int k = 0; k < 4; k++) nxt[k] = __ldcs(&g_erec[en + k]);
        }
        uint2 fw[4];
#pragma unroll
        for (int k = 0; k < 4; k++)
            fw[k] = __ldcs(reinterpret_cast<const uint2*>(&g_feath[(int)cur[k].w * 64 + lane * 2]));
#pragma unroll
        for (int k = 0; k < 4; k++) {
            float p = __uint_as_float(cur[k].x);
            int i = (int)p;
            float f = p - (float)i;
            float2 t0 = __half22float2(g_tab1h[i * 32 + lane]);
            float2 t1 = __half22float2(g_tab1h[(i + 1) * 32 + lane]);
            float2 f0 = __half22float2(*reinterpret_cast<const __half2*>(&fw[k].x));
            float2 f1 = __half22float2(*reinterpret_cast<const __half2*>(&fw[k].y));
            float2 sh = __half22float2(*reinterpret_cast<const __half2*>(&cur[k].y));
            float sh2 = __half2float(__ushort_as_half((unsigned short)(cur[k].z & 0xffffu)));
            float w1 = fmaf(f, t1.x - t0.x, t0.x);
            float w2 = fmaf(f, t1.y - t0.y, t0.y);
            a0 += w1 * f0.x;
            a1 += w2 * (f0.y * sh.x + f1.x * sh.y + f1.y * sh2);
        }
        if (hn) {
#pragma unroll
            for (int k = 0; k < 4; k++) cur[k] = nxt[k];
        }
        e = en;
    }
    for (; e < end; e++) {
        uint4 rA = __ldcs(&g_erec[e]);
        float p = __uint_as_float(rA.x);
        int i = (int)p;
        float f = p - (float)i;
        float2 t0 = __half22float2(g_tab1h[i * 32 + lane]);
        float2 t1 = __half22float2(g_tab1h[(i + 1) * 32 + lane]);
        uint2 fwA = __ldcs(reinterpret_cast<const uint2*>(&g_feath[(int)rA.w * 64 + lane * 2]));
        float2 f0 = __half22float2(*reinterpret_cast<const __half2*>(&fwA.x));
        float2 f1 = __half22float2(*reinterpret_cast<const __half2*>(&fwA.y));
        float2 sh = __half22float2(*reinterpret_cast<const __half2*>(&rA.y));
        float sh2 = __half2float(__ushort_as_half((unsigned short)(rA.z & 0xffffu)));
        float w1 = fmaf(f, t1.x - t0.x, t0.x);
        float w2 = fmaf(f, t1.y - t0.y, t0.y);
        a0 += w1 * f0.x;
        a1 += w2 * (f0.y * sh.x + f1.x * sh.y + f1.y * sh2);
    }
    // ---- fused lin2 (scalar half only) + residual + readout ----
    float a1s = a1 * 0.5773502691896258f;
    const float* W2s = w_lin2_s + 4096;  // l=1
    float s0 = 0.f;
#pragma unroll 4
    for (int j = 0; j < 32; j++) {
        float xj = __shfl_sync(0xffffffffu, a0, j);
        s0 += xj * W2s[j * 64 + lane];
    }
#pragma unroll 4
    for (int j = 32; j < 64; j++) {
        float xj = __shfl_sync(0xffffffffu, a1s, j - 32);
        s0 += xj * W2s[j * 64 + lane];
    }
    const float SC_ = 0.0078125f;
    float hs = silu(s0 * SC_ + g_res1s[n * 32 + lane]);
    float z = hs * g_wcomb[lane];
    z += __shfl_xor_sync(0xffffffffu, z, 16);
    z += __shfl_xor_sync(0xffffffffu, z, 8);
    z += __shfl_xor_sync(0xffffffffu, z, 4);
    z += __shfl_xor_sync(0xffffffffu, z, 2);
    z += __shfl_xor_sync(0xffffffffu, z, 1);
    if (lane == 0) out[n] = z * (0.17677669529663687f * 0.25f);
}

// ---------------- launch ----------------
extern "C" void kernel_launch(void* const* d_in, const int* in_sizes, int n_in,
                              void* d_out, int out_size) {
    const float* edge_vectors = (const float*)d_in[0];
    const int* species        = (const int*)d_in[1];
    const int* senders        = (const int*)d_in[2];
    const int* receivers      = (const int*)d_in[3];
    const float* embed_w      = (const float*)d_in[4];
    const float* w_res_s      = (const float*)d_in[5];
    const float* w_lin1_s     = (const float*)d_in[7];
    const float* w_lin1_v     = (const float*)d_in[8];
    const float* mlp_w0       = (const float*)d_in[9];
    const float* mlp_w1       = (const float*)d_in[10];
    const float* mlp_w2       = (const float*)d_in[11];
    const float* w_lin2_s     = (const float*)d_in[12];
    const float* w_lin2_v     = (const float*)d_in[13];
    const float* w_out1       = (const float*)d_in[14];
    const float* w_out2       = (const float*)d_in[15];
    float* out = (float*)d_out;

    static cudaStream_t s2 = nullptr;
    static cudaEvent_t evA = nullptr, evB = nullptr;
    if (!s2) {
        cudaStreamCreateWithFlags(&s2, cudaStreamNonBlocking);
        cudaEventCreateWithFlags(&evA, cudaEventDisableTiming);
        cudaEventCreateWithFlags(&evB, cudaEventDisableTiming);
    }

    void* zb_ptr = nullptr;
    cudaGetSymbolAddress(&zb_ptr, g_zb);

    const int EB256 = (EE + 255) / 256;
    const int GPB = (NN + 3) / 4;          // fused gathers: 128-thr blocks, warp per node
    const int WPB8 = (NN / 8 + 7) / 8;

    // fork: side stream builds LUT + species-pure prep, overlapping the CSR chain
    cudaEventRecord(evA, 0);
    cudaStreamWaitEvent(s2, evA, 0);
    k_build_table<<<dim3(TBINS, 2), 128, 0, s2>>>(mlp_w0, mlp_w1, mlp_w2);
    k_spec0<<<1, 192, 0, s2>>>(embed_w, w_lin1_s, w_res_s, w_out1, w_out2);
    cudaEventRecord(evB, s2);

    // main chain: CSR build
    cudaMemsetAsync(zb_ptr, 0, (NN + 16 + NODE_BLOCKS) * sizeof(int));
    k_hist<<<EB256, 256>>>(edge_vectors, receivers, species);
    k_scan<<<NODE_BLOCKS, 256>>>();
    k_scatter<<<EB256, 256>>>(edge_vectors, senders, receivers, species);

    // join, then fused layers
    cudaStreamWaitEvent(0, evB, 0);
    k_gfused0<<<GPB, 128>>>(species, w_lin2_s, w_lin2_v);
    k_prep1<<<WPB8, 256>>>(species, w_res_s, w_lin1_s, w_lin1_v);
    k_gfused1<<<GPB, 128>>>(w_lin2_s, out);
}

// round 12
// speedup vs baseline: 1.2069x; 1.2069x over previous
#include <cuda_runtime.h>
#include <cuda_fp16.h>

#define NN 50000
#define EE 800000
#define SC 5
#define NBC 8
#define HC 64
#define NWC 128
#define TBINS 1024
#define RMAXF 5.0f

#define NODE_BLOCKS 196         // 196*256 >= NN

// ---------------- device scratch ----------------
// g_zb layout: [0,NN) degree->cursor; [NN+16, NN+16+NODE_BLOCKS) lookback states
__device__ int g_zb[NN + 16 + NODE_BLOCKS];
__device__ int g_off[NN + 1];
__device__ uint4 g_erec[EE];             // packed CSR edge record: p | sh01 | (spec<<16|sh2) | sender
__device__ __half2 g_feath[NN * 64];     // layer1 feats: (es,ev0),(ev1,ev2)
__device__ float g_res1s[NN * 32];
__device__ __half2 g_tab0h[TBINS * 32];  // layer0 LUT (w1, w3)  — 128 KB, L1-resident
__device__ __half2 g_tab1h[TBINS * 32];  // layer1 LUT (w1, w2)
__device__ float g_s0hsl[SC * 32];
__device__ float g_s0res[SC * 64];
__device__ float g_wcomb[32];            // readout combined weights

__device__ __forceinline__ float silu(float x) { return x / (1.0f + __expf(-x)); }

// ---------------- hist: receiver degrees ----------------
__global__ void k_hist(const float* __restrict__ evec, const int* __restrict__ recv) {
    int e = blockIdx.x * blockDim.x + threadIdx.x;
    if (e >= EE) return;
    float x = evec[e * 3], y = evec[e * 3 + 1], z = evec[e * 3 + 2];
    if (x * x + y * y + z * z < RMAXF * RMAXF) atomicAdd(&g_zb[recv[e]], 1);
}

// ---------------- single-pass scan, warp-parallel decoupled lookback ----------------
#define FLAGP 0x40000000u
#define FLAGX 0x80000000u
#define VALM  0x3FFFFFFFu

__global__ void __launch_bounds__(256) k_scan() {
    __shared__ int ws[8];
    __shared__ int s_tot, s_off;
    int b = blockIdx.x, t = threadIdx.x;
    int lane = t & 31, wid = t >> 5;
    int idx = b * 256 + t;
    int v = (idx < NN) ? g_zb[idx] : 0;
    int x = v;
#pragma unroll
    for (int d = 1; d < 32; d <<= 1) {
        int y = __shfl_up_sync(0xffffffffu, x, d);
        if (lane >= d) x += y;
    }
    if (lane == 31) ws[wid] = x;
    __syncthreads();
    if (wid == 0 && lane < 8) {
        int s = ws[lane];
#pragma unroll
        for (int d = 1; d < 8; d <<= 1) {
            int y = __shfl_up_sync(0xffu, s, d);
            if (lane >= d) s += y;
        }
        ws[lane] = s;
    }
    __syncthreads();
    int incl = x + (wid > 0 ? ws[wid - 1] : 0);
    if (t == 255) s_tot = incl;
    __syncthreads();
    unsigned int* look = reinterpret_cast<unsigned int*>(&g_zb[NN + 16]);
    if (wid == 0) {
        if (b == 0) {
            if (lane == 0) {
                s_off = 0;
                atomicExch(&look[0], (unsigned)s_tot | FLAGX);
            }
        } else {
            if (lane == 0) atomicExch(&look[b], (unsigned)s_tot | FLAGP);
            int run = 0, j = b;
            while (true) {
                int pidx = j - 1 - lane;
                unsigned st = FLAGX;   // OOB lanes contribute value 0 with X-flag
                if (pidx >= 0) {
                    while ((((st = atomicAdd(&look[pidx], 0u))) & (FLAGP | FLAGX)) == 0u)
                        __nanosleep(32);
                }
                unsigned xmask = __ballot_sync(0xffffffffu, (st & FLAGX) != 0u);
                int val = (int)(st & VALM);
                if (xmask) {
                    int firstx = __ffs(xmask) - 1;
                    int contrib = (lane <= firstx) ? val : 0;
#pragma unroll
                    for (int d = 16; d > 0; d >>= 1)
                        contrib += __shfl_xor_sync(0xffffffffu, contrib, d);
                    run += contrib;
                    break;
                } else {
                    int contrib = val;
#pragma unroll
                    for (int d = 16; d > 0; d >>= 1)
                        contrib += __shfl_xor_sync(0xffffffffu, contrib, d);
                    run += contrib;
                    j -= 32;
                }
            }
            if (lane == 0) {
                s_off = run;
                atomicExch(&look[b], (unsigned)(run + s_tot) | FLAGX);
            }
        }
        if (b == NODE_BLOCKS - 1 && lane == 0) g_off[NN] = s_off + s_tot;
    }
    __syncthreads();
    if (idx < NN) {
        int o = incl - v + s_off;
        g_off[idx] = o;
        g_zb[idx] = o;   // cursor for scatter
    }
}

// ---------------- scatter: packed 16B record ----------------
__global__ void k_scatter(const float* __restrict__ evec, const int* __restrict__ senders,
                          const int* __restrict__ recv, const int* __restrict__ species) {
    int e = blockIdx.x * blockDim.x + threadIdx.x;
    if (e >= EE) return;
    float x = evec[e * 3], y = evec[e * 3 + 1], z = evec[e * 3 + 2];
    float r2 = x * x + y * y + z * z;
    if (r2 >= RMAXF * RMAXF) return;
    float r = sqrtf(r2 + 1e-12f);
    float ir = 1.0f / r;
    const float SQ3 = 1.7320508075688772f;
    int s = senders[e];
    int pos = atomicAdd(&g_zb[recv[e]], 1);
    uint4 rec;
    rec.x = __float_as_uint(r * ((float)(TBINS - 1) / RMAXF));
    __half2 h01 = __floats2half2_rn(SQ3 * x * ir, SQ3 * y * ir);
    rec.y = *reinterpret_cast<unsigned int*>(&h01);
    __half h2 = __float2half_rn(SQ3 * z * ir);
    rec.z = ((unsigned int)species[s] << 16) | (unsigned int)__half_as_ushort(h2);
    rec.w = (unsigned int)s;
    g_erec[pos] = rec;
}

// ---------------- radial-MLP LUT (fp16 rows, both layers) ----------------
__global__ void k_build_table(const float* __restrict__ mlp_w0,
                              const float* __restrict__ mlp_w1,
                              const float* __restrict__ mlp_w2) {
    __shared__ float a1[HC];
    __shared__ float a2[HC];
    __shared__ float eemb[NBC];
    __shared__ float sacc[128];
    int bin = blockIdx.x;
    int l = blockIdx.y;
    int tid = threadIdx.x;
    const float* w0 = mlp_w0 + l * NBC * HC;
    const float* w1 = mlp_w1 + l * HC * HC;
    const float* w2 = mlp_w2 + l * HC * NWC;
    if (tid < NBC) {
        float r = (float)bin * (RMAXF / (float)(TBINS - 1));
        float rs = fmaxf(r, 1e-6f);
        float ir = 1.0f / rs;
        float xr = rs * (1.0f / RMAXF);
        float x3 = xr * xr * xr, x6 = x3 * x3, x7 = x6 * xr, x8 = x7 * xr;
        float env = 1.0f - 28.0f * x6 + 48.0f * x7 - 21.0f * x8;
        const float PI_ = 3.14159265358979323846f;
        eemb[tid] = 0.6324555320336759f * ir * env * sinf(PI_ * xr * (float)(tid + 1));
    }
    __syncthreads();
    if (tid < HC) {
        float acc = 0.f;
#pragma unroll
        for (int k = 0; k < NBC; k++) acc += eemb[k] * w0[k * HC + tid];
        a1[tid] = silu(acc * 0.35355339059327373f);
    }
    __syncthreads();
    if (tid < HC) {
        float acc = 0.f;
#pragma unroll 8
        for (int k = 0; k < HC; k++) acc += a1[k] * w1[k * HC + tid];
        a2[tid] = silu(acc * 0.125f);
    }
    __syncthreads();
    {
        float acc = 0.f;
#pragma unroll 8
        for (int k = 0; k < HC; k++) acc += a2[k] * w2[k * NWC + tid];
        sacc[tid] = acc;
    }
    __syncthreads();
    if (tid < 32) {
        if (l == 0)
            g_tab0h[bin * 32 + tid] = __floats2half2_rn(sacc[tid], sacc[64 + tid]);
        else
            g_tab1h[bin * 32 + tid] = __floats2half2_rn(sacc[tid], sacc[32 + tid]);
    }
}

// ---------------- layer0 species-pure node prep + readout wcomb ----------------
__global__ void k_spec0(const float* __restrict__ embed_w,
                        const float* __restrict__ w_lin1_s,
                        const float* __restrict__ w_res_s,
                        const float* __restrict__ w_out1,
                        const float* __restrict__ w_out2) {
    int w = threadIdx.x >> 5, lane = threadIdx.x & 31;
    if (w < SC) {
        float a_hs = 0.f, a_rs0 = 0.f, a_rs1 = 0.f;
#pragma unroll 4
        for (int u = 0; u < 32; u++) {
            float x = embed_w[w * 32 + u] * 0.4472135954999579f;
            a_hs += x * w_lin1_s[u * 32 + lane];
            const float* rs = w_res_s + (size_t)(u * SC + w) * 64;
            a_rs0 += x * rs[lane];
            a_rs1 += x * rs[32 + lane];
        }
        g_s0hsl[w * 32 + lane] = a_hs * 0.17677669529663687f;
        g_s0res[w * 64 + lane] = a_rs0 * 0.07905694150420949f;
        g_s0res[w * 64 + 32 + lane] = a_rs1 * 0.07905694150420949f;
    } else if (w == SC) {
        float acc = 0.f;
#pragma unroll
        for (int k = 0; k < 16; k++) acc += w_out1[lane * 16 + k] * w_out2[k];
        g_wcomb[lane] = acc;
    }
}

// ---------------- fused layer0: gather + lin2 + gate + lin1(l=1) + res1 ----------------
__global__ void __launch_bounds__(128) k_gfused0(const int* __restrict__ species,
                                                 const float* __restrict__ w_lin2_s,
                                                 const float* __restrict__ w_lin2_v,
                                                 const float* __restrict__ w_lin1_s,
                                                 const float* __restrict__ w_lin1_v,
                                                 const float* __restrict__ w_res_s) {
    int n = (blockIdx.x * blockDim.x + threadIdx.x) >> 5;
    int lane = threadIdx.x & 31;
    if (n >= NN) return;
    float sr[SC];
#pragma unroll
    for (int s = 0; s < SC; s++) sr[s] = g_s0hsl[s * 32 + lane];
    int e = g_off[n], end = g_off[n + 1];
    float a0 = 0.f, c3x = 0.f, c3y = 0.f, c3z = 0.f;
    for (; e + 3 < end; e += 4) {
        uint4 r[4];
#pragma unroll
        for (int k = 0; k < 4; k++) r[k] = __ldcs(&g_erec[e + k]);
#pragma unroll
        for (int k = 0; k < 4; k++) {
            float p = __uint_as_float(r[k].x);
            int i = (int)p;
            float f = p - (float)i;
            float2 t0 = __half22float2(g_tab0h[i * 32 + lane]);
            float2 t1 = __half22float2(g_tab0h[(i + 1) * 32 + lane]);
            float2 sh = __half22float2(*reinterpret_cast<const __half2*>(&r[k].y));
            float sh2 = __half2float(__ushort_as_half((unsigned short)(r[k].z & 0xffffu)));
            int sp = r[k].z >> 16;
            float es = sr[0];
            es = (sp == 1) ? sr[1] : es;
            es = (sp == 2) ? sr[2] : es;
            es = (sp == 3) ? sr[3] : es;
            es = (sp == 4) ? sr[4] : es;
            float w1 = fmaf(f, t1.x - t0.x, t0.x);
            float w3 = fmaf(f, t1.y - t0.y, t0.y);
            a0 += w1 * es;
            float wv = w3 * es;
            c3x += wv * sh.x; c3y += wv * sh.y; c3z += wv * sh2;
        }
    }
    for (; e < end; e++) {
        uint4 rA = __ldcs(&g_erec[e]);
        float p = __uint_as_float(rA.x);
        int i = (int)p;
        float f = p - (float)i;
        float2 t0 = __half22float2(g_tab0h[i * 32 + lane]);
        float2 t1 = __half22float2(g_tab0h[(i + 1) * 32 + lane]);
        float2 sh = __half22float2(*reinterpret_cast<const __half2*>(&rA.y));
        float sh2 = __half2float(__ushort_as_half((unsigned short)(rA.z & 0xffffu)));
        int sp = rA.z >> 16;
        float es = sr[0];
        es = (sp == 1) ? sr[1] : es;
        es = (sp == 2) ? sr[2] : es;
        es = (sp == 3) ? sr[3] : es;
        es = (sp == 4) ? sr[4] : es;
        float w1 = fmaf(f, t1.x - t0.x, t0.x);
        float w3 = fmaf(f, t1.y - t0.y, t0.y);
        a0 += w1 * es;
        float wv = w3 * es;
        c3x += wv * sh.x; c3y += wv * sh.y; c3z += wv * sh2;
    }
    // ---- lin2 + residual + gate via shuffle contraction ----
    float s0 = 0.f, s1 = 0.f, v0 = 0.f, v1 = 0.f, v2 = 0.f;
#pragma unroll 4
    for (int j = 0; j < 32; j++) {
        float xj = __shfl_sync(0xffffffffu, a0, j);
        float c0 = __shfl_sync(0xffffffffu, c3x, j);
        float c1 = __shfl_sync(0xffffffffu, c3y, j);
        float c2 = __shfl_sync(0xffffffffu, c3z, j);
        float wa = w_lin2_s[j * 64 + lane];
        float wb = w_lin2_s[j * 64 + 32 + lane];
        float wc = w_lin2_v[j * 32 + lane];
        s0 += xj * wa;
        s1 += xj * wb;
        v0 += c0 * wc; v1 += c1 * wc; v2 += c2 * wc;
    }
    const float SC_ = 0.0078125f;
    int sp = species[n];
    float hs = silu(s0 * SC_ + g_s0res[sp * 64 + lane]);
    float gate = silu(s1 * SC_ + g_s0res[sp * 64 + 32 + lane]);
    float hv0 = v0 * SC_ * gate;
    float hv1 = v1 * SC_ * gate;
    float hv2 = v2 * SC_ * gate;
    // ---- fused layer1 prep: lin1 + residual via second shuffle contraction ----
    const float* Wl1s = w_lin1_s + 1024;
    const float* Wl1v = w_lin1_v + 1024;
    float a_hs = 0.f, a_rs0 = 0.f, ahv0 = 0.f, ahv1 = 0.f, ahv2 = 0.f;
#pragma unroll 4
    for (int j = 0; j < 32; j++) {
        float xs = __shfl_sync(0xffffffffu, hs, j);
        float x0 = __shfl_sync(0xffffffffu, hv0, j);
        float x1 = __shfl_sync(0xffffffffu, hv1, j);
        float x2 = __shfl_sync(0xffffffffu, hv2, j);
        float ws = Wl1s[j * 32 + lane];
        float wv = Wl1v[j * 32 + lane];
        float wr = w_res_s[(size_t)(((32 + j) * SC) + sp) * 64 + lane];
        a_hs += xs * ws;
        a_rs0 += xs * wr;
        ahv0 += x0 * wv; ahv1 += x1 * wv; ahv2 += x2 * wv;
    }
    const float IS32 = 0.17677669529663687f;
    const float IS160 = 0.07905694150420949f;
    g_feath[n * 64 + lane * 2] = __floats2half2_rn(a_hs * IS32, ahv0 * IS32);
    g_feath[n * 64 + lane * 2 + 1] = __floats2half2_rn(ahv1 * IS32, ahv2 * IS32);
    g_res1s[n * 32 + lane] = a_rs0 * IS160;
}

// ---------------- fused layer1: gather + lin2 + residual + readout ----------------
__global__ void __launch_bounds__(128) k_gfused1(const float* __restrict__ w_lin2_s,
                                                 float* __restrict__ out) {
    int n = (blockIdx.x * blockDim.x + threadIdx.x) >> 5;
    int lane = threadIdx.x & 31;
    if (n >= NN) return;
    int e = g_off[n], end = g_off[n + 1];
    float a0 = 0.f, a1 = 0.f;
    for (; e + 3 < end; e += 4) {
        uint4 r[4];
        uint2 fw[4];
#pragma unroll
        for (int k = 0; k < 4; k++) r[k] = __ldcs(&g_erec[e + k]);
#pragma unroll
        for (int k = 0; k < 4; k++)
            fw[k] = __ldcs(reinterpret_cast<const uint2*>(&g_feath[(int)r[k].w * 64 + lane * 2]));
#pragma unroll
        for (int k = 0; k < 4; k++) {
            float p = __uint_as_float(r[k].x);
            int i = (int)p;
            float f = p - (float)i;
            float2 t0 = __half22float2(g_tab1h[i * 32 + lane]);
            float2 t1 = __half22float2(g_tab1h[(i + 1) * 32 + lane]);
            float2 f0 = __half22float2(*reinterpret_cast<const __half2*>(&fw[k].x));
            float2 f1 = __half22float2(*reinterpret_cast<const __half2*>(&fw[k].y));
            float2 sh = __half22float2(*reinterpret_cast<const __half2*>(&r[k].y));
            float sh2 = __half2float(__ushort_as_half((unsigned short)(r[k].z & 0xffffu)));
            float w1 = fmaf(f, t1.x - t0.x, t0.x);
            float w2 = fmaf(f, t1.y - t0.y, t0.y);
            a0 += w1 * f0.x;
            a1 += w2 * (f0.y * sh.x + f1.x * sh.y + f1.y * sh2);
        }
    }
    for (; e < end; e++) {
        uint4 rA = __ldcs(&g_erec[e]);
        float p = __uint_as_float(rA.x);
        int i = (int)p;
        float f = p - (float)i;
        float2 t0 = __half22float2(g_tab1h[i * 32 + lane]);
        float2 t1 = __half22float2(g_tab1h[(i + 1) * 32 + lane]);
        uint2 fwA = __ldcs(reinterpret_cast<const uint2*>(&g_feath[(int)rA.w * 64 + lane * 2]));
        float2 f0 = __half22float2(*reinterpret_cast<const __half2*>(&fwA.x));
        float2 f1 = __half22float2(*reinterpret_cast<const __half2*>(&fwA.y));
        float2 sh = __half22float2(*reinterpret_cast<const __half2*>(&rA.y));
        float sh2 = __half2float(__ushort_as_half((unsigned short)(rA.z & 0xffffu)));
        float w1 = fmaf(f, t1.x - t0.x, t0.x);
        float w2 = fmaf(f, t1.y - t0.y, t0.y);
        a0 += w1 * f0.x;
        a1 += w2 * (f0.y * sh.x + f1.x * sh.y + f1.y * sh2);
    }
    // ---- fused lin2 (scalar half only) + residual + readout ----
    float a1s = a1 * 0.5773502691896258f;
    const float* W2s = w_lin2_s + 4096;  // l=1
    float s0 = 0.f;
#pragma unroll 4
    for (int j = 0; j < 32; j++) {
        float xj = __shfl_sync(0xffffffffu, a0, j);
        s0 += xj * W2s[j * 64 + lane];
    }
#pragma unroll 4
    for (int j = 32; j < 64; j++) {
        float xj = __shfl_sync(0xffffffffu, a1s, j - 32);
        s0 += xj * W2s[j * 64 + lane];
    }
    const float SC_ = 0.0078125f;
    float hs = silu(s0 * SC_ + g_res1s[n * 32 + lane]);
    float z = hs * g_wcomb[lane];
    z += __shfl_xor_sync(0xffffffffu, z, 16);
    z += __shfl_xor_sync(0xffffffffu, z, 8);
    z += __shfl_xor_sync(0xffffffffu, z, 4);
    z += __shfl_xor_sync(0xffffffffu, z, 2);
    z += __shfl_xor_sync(0xffffffffu, z, 1);
    if (lane == 0) out[n] = z * (0.17677669529663687f * 0.25f);
}

// ---------------- launch ----------------
extern "C" void kernel_launch(void* const* d_in, const int* in_sizes, int n_in,
                              void* d_out, int out_size) {
    const float* edge_vectors = (const float*)d_in[0];
    const int* species        = (const int*)d_in[1];
    const int* senders        = (const int*)d_in[2];
    const int* receivers      = (const int*)d_in[3];
    const float* embed_w      = (const float*)d_in[4];
    const float* w_res_s      = (const float*)d_in[5];
    const float* w_lin1_s     = (const float*)d_in[7];
    const float* w_lin1_v     = (const float*)d_in[8];
    const float* mlp_w0       = (const float*)d_in[9];
    const float* mlp_w1       = (const float*)d_in[10];
    const float* mlp_w2       = (const float*)d_in[11];
    const float* w_lin2_s     = (const float*)d_in[12];
    const float* w_lin2_v     = (const float*)d_in[13];
    const float* w_out1       = (const float*)d_in[14];
    const float* w_out2       = (const float*)d_in[15];
    float* out = (float*)d_out;

    static cudaStream_t s2 = nullptr;
    static cudaEvent_t evA = nullptr, evB = nullptr;
    if (!s2) {
        cudaStreamCreateWithFlags(&s2, cudaStreamNonBlocking);
        cudaEventCreateWithFlags(&evA, cudaEventDisableTiming);
        cudaEventCreateWithFlags(&evB, cudaEventDisableTiming);
    }

    void* zb_ptr = nullptr;
    cudaGetSymbolAddress(&zb_ptr, g_zb);

    const int EB256 = (EE + 255) / 256;
    const int GPB = (NN + 3) / 4;          // fused gathers: 128-thr blocks, warp per node

    // fork: side stream builds LUT + species-pure prep, overlapping the CSR chain
    cudaEventRecord(evA, 0);
    cudaStreamWaitEvent(s2, evA, 0);
    k_build_table<<<dim3(TBINS, 2), 128, 0, s2>>>(mlp_w0, mlp_w1, mlp_w2);
    k_spec0<<<1, 192, 0, s2>>>(embed_w, w_lin1_s, w_res_s, w_out1, w_out2);
    cudaEventRecord(evB, s2);

    // main chain: CSR build
    cudaMemsetAsync(zb_ptr, 0, (NN + 16 + NODE_BLOCKS) * sizeof(int));
    k_hist<<<EB256, 256>>>(edge_vectors, receivers);
    k_scan<<<NODE_BLOCKS, 256>>>();
    k_scatter<<<EB256, 256>>>(edge_vectors, senders, receivers, species);

    // join, then fused layers
    cudaStreamWaitEvent(0, evB, 0);
    k_gfused0<<<GPB, 128>>>(species, w_lin2_s, w_lin2_v, w_lin1_s, w_lin1_v, w_res_s);
    k_gfused1<<<GPB, 128>>>(w_lin2_s, out);
}